// round 1
// baseline (speedup 1.0000x reference)
#include <cuda_runtime.h>
#include <math.h>

#define ATOMS 48
#define BLK 128

// cos/sin of SHF_Z[z] = (2z+1)*pi/16
__device__ __constant__ float COSZ[8] = {
     0.98078528040323044913f,  0.83146961230254523708f,
     0.55557023301960222474f,  0.19509032201612826785f,
    -0.19509032201612826785f, -0.55557023301960222474f,
    -0.83146961230254523708f, -0.98078528040323044913f };
__device__ __constant__ float SINZ[8] = {
     0.19509032201612826785f,  0.55557023301960222474f,
     0.83146961230254523708f,  0.98078528040323044913f,
     0.98078528040323044913f,  0.83146961230254523708f,
     0.55557023301960222474f,  0.19509032201612826785f };

// PAIR_IDX for 4 species (upper-triangular enumeration, symmetric)
__device__ __constant__ int PAIRT[4][4] = {
    {0,1,2,3},{1,4,5,6},{2,5,7,8},{3,6,8,9} };

__global__ void __launch_bounds__(BLK)
aev_kernel(const int* __restrict__ species, const float* __restrict__ coords,
           float* __restrict__ aev_out, float* __restrict__ sp_out)
{
    const int i = blockIdx.x;          // atom within batch
    const int b = blockIdx.y;          // batch
    const int A = gridDim.x;           // 48
    const int tid = threadIdx.x;

    __shared__ float cx[ATOMS], cy[ATOMS], cz[ATOMS];
    __shared__ int   sp[ATOMS];
    __shared__ float rad[64];
    __shared__ float ang[320];
    __shared__ float nvx[ATOMS], nvy[ATOMS], nvz[ATOMS], nd[ATOMS], nfc[ATOMS];
    __shared__ int   nsp[ATOMS];
    __shared__ int   ncnt;

    const float* cb = coords + (size_t)b * A * 3;
    if (tid < A) {
        cx[tid] = cb[tid*3 + 0];
        cy[tid] = cb[tid*3 + 1];
        cz[tid] = cb[tid*3 + 2];
        sp[tid] = species[b*A + tid];
    }
    for (int t = tid; t < 64;  t += BLK) rad[t] = 0.0f;
    for (int t = tid; t < 320; t += BLK) ang[t] = 0.0f;
    if (tid == 0) ncnt = 0;
    __syncthreads();

    const float xi = cx[i], yi = cy[i], zi = cz[i];

    // ---- radial pass + neighbor-list build (one thread per neighbor j) ----
    if (tid < A && tid != i) {
        float dx = cx[tid] - xi;
        float dy = cy[tid] - yi;
        float dz = cz[tid] - zi;
        float d  = sqrtf(dx*dx + dy*dy + dz*dz);
        if (d <= 5.2f) {
            float fcr = 0.5f * cospif(d / 5.2f) + 0.5f;
            int s = sp[tid];
            float* radp = &rad[s * 16];
            #pragma unroll
            for (int r = 0; r < 16; r++) {
                float u = d - (0.9f + 0.26875f * (float)r);
                atomicAdd(&radp[r], 0.25f * expf(-16.0f * u * u) * fcr);
            }
        }
        if (d <= 3.5f) {
            float fca = 0.5f * cospif(d / 3.5f) + 0.5f;
            int idx = atomicAdd(&ncnt, 1);
            nvx[idx] = dx; nvy[idx] = dy; nvz[idx] = dz;
            nd[idx]  = d;  nfc[idx] = fca; nsp[idx] = sp[tid];
        }
    }
    __syncthreads();

    // ---- angular pass: all unordered neighbor pairs ----
    const int M = ncnt;
    const int T = M * (M - 1) / 2;
    const float fm = (float)M - 0.5f;
    for (int t = tid; t < T; t += BLK) {
        // linear index -> (l1 < l2)
        int l1 = (int)(fm - sqrtf(fm * fm - 2.0f * (float)t));
        if (l1 < 0) l1 = 0;
        while (l1 * M - l1 * (l1 + 1) / 2 > t) l1--;
        while ((l1 + 1) * M - (l1 + 1) * (l1 + 2) / 2 <= t) l1++;
        int l2 = l1 + 1 + (t - (l1 * M - l1 * (l1 + 1) / 2));

        float d1 = nd[l1], d2 = nd[l2];
        float dot = nvx[l1]*nvx[l2] + nvy[l1]*nvy[l2] + nvz[l1]*nvz[l2];
        float ct = 0.95f * dot / (d1 * d2);          // |ct| <= 0.95
        float st = sqrtf(fmaxf(1.0f - ct * ct, 0.0f));
        float w  = 2.0f * nfc[l1] * nfc[l2];
        float avg = 0.5f * (d1 + d2);

        float f2v[4];
        #pragma unroll
        for (int a = 0; a < 4; a++) {
            float u = avg - (0.9f + 0.65f * (float)a);
            f2v[a] = w * expf(-8.0f * u * u);
        }

        int p = PAIRT[nsp[l1]][nsp[l2]];
        float* angp = &ang[p * 32];
        #pragma unroll
        for (int z = 0; z < 8; z++) {
            // cos(acos(ct) - shfz) = ct*cos(shfz) + st*sin(shfz)
            float c  = ct * COSZ[z] + st * SINZ[z];
            float b1 = 0.5f * (1.0f + c);
            float b2 = b1 * b1;
            float b4 = b2 * b2;
            float b8 = b4 * b4;
            float b16 = b8 * b8;
            float f1 = b16 * b16;                    // b1^32
            #pragma unroll
            for (int a = 0; a < 4; a++)
                atomicAdd(&angp[a * 8 + z], f2v[a] * f1);
        }
    }
    __syncthreads();

    // ---- write out ----
    float* o = aev_out + (size_t)(b * A + i) * 384;
    for (int t = tid; t < 64;  t += BLK) o[t]      = rad[t];
    for (int t = tid; t < 320; t += BLK) o[64 + t] = ang[t];
    if (sp_out != nullptr && tid == 0)
        sp_out[b * A + i] = (float)sp[i];
}

extern "C" void kernel_launch(void* const* d_in, const int* in_sizes, int n_in,
                              void* d_out, int out_size)
{
    const int*   species = (const int*)d_in[0];
    const float* coords  = (const float*)d_in[1];

    const int BA = in_sizes[0];     // B*A
    const int A  = ATOMS;           // 48 per reference
    const int B  = BA / A;
    const int aev_total = BA * 384;

    float* out    = (float*)d_out;
    float* sp_out = nullptr;
    float* aev    = out;
    if (out_size >= aev_total + BA) {   // tuple output: species first, then aevs
        sp_out = out;
        aev    = out + BA;
    }

    dim3 grid(A, B);
    aev_kernel<<<grid, BLK>>>(species, coords, aev, sp_out);
}

// round 2
// speedup vs baseline: 1.1026x; 1.1026x over previous
#include <cuda_runtime.h>
#include <math.h>

#define ATOMS 48
#define BLK 128

// cos/sin of SHF_Z[z] = (2z+1)*pi/16
__device__ __constant__ float COSZ[8] = {
     0.98078528040323044913f,  0.83146961230254523708f,
     0.55557023301960222474f,  0.19509032201612826785f,
    -0.19509032201612826785f, -0.55557023301960222474f,
    -0.83146961230254523708f, -0.98078528040323044913f };
__device__ __constant__ float SINZ[8] = {
     0.19509032201612826785f,  0.55557023301960222474f,
     0.83146961230254523708f,  0.98078528040323044913f,
     0.98078528040323044913f,  0.83146961230254523708f,
     0.55557023301960222474f,  0.19509032201612826785f };

// PAIR_IDX for 4 species (upper-triangular enumeration, symmetric)
__device__ __constant__ int PAIRT[4][4] = {
    {0,1,2,3},{1,4,5,6},{2,5,7,8},{3,6,8,9} };

__global__ void __launch_bounds__(BLK)
aev_kernel(const int* __restrict__ species, const float* __restrict__ coords,
           float* __restrict__ aev_out, float* __restrict__ sp_out)
{
    const int i = blockIdx.x;          // atom within batch
    const int b = blockIdx.y;          // batch
    const int A = gridDim.x;           // 48
    const int tid = threadIdx.x;
    const int slice = tid & 3;         // 4-way accumulator slicing

    __shared__ float cx[ATOMS], cy[ATOMS], cz[ATOMS];
    __shared__ int   sp[ATOMS];
    __shared__ float rad4[4][64];
    __shared__ float ang4[4][320];
    __shared__ float nvx[ATOMS], nvy[ATOMS], nvz[ATOMS];
    __shared__ float nd[ATOMS], nrd[ATOMS], nfc[ATOMS];
    __shared__ int   nsp[ATOMS];
    __shared__ int   ncnt;

    const float* cb = coords + (size_t)b * A * 3;
    if (tid < A) {
        cx[tid] = cb[tid*3 + 0];
        cy[tid] = cb[tid*3 + 1];
        cz[tid] = cb[tid*3 + 2];
        sp[tid] = species[b*A + tid];
    }
    for (int t = tid; t < 4*64;  t += BLK) ((float*)rad4)[t] = 0.0f;
    for (int t = tid; t < 4*320; t += BLK) ((float*)ang4)[t] = 0.0f;
    if (tid == 0) ncnt = 0;
    __syncthreads();

    const float xi = cx[i], yi = cy[i], zi = cz[i];

    // ---- radial pass + neighbor-list build (one thread per neighbor j) ----
    if (tid < A && tid != i) {
        float dx = cx[tid] - xi;
        float dy = cy[tid] - yi;
        float dz = cz[tid] - zi;
        float d  = sqrtf(dx*dx + dy*dy + dz*dz);
        if (d <= 5.2f) {
            float fcr = 0.5f * cospif(d / 5.2f) + 0.5f;
            float* radp = &rad4[slice][sp[tid] * 16];
            #pragma unroll
            for (int r = 0; r < 16; r++) {
                float u = d - (0.9f + 0.26875f * (float)r);
                atomicAdd(&radp[r], 0.25f * __expf(-16.0f * u * u) * fcr);
            }
        }
        if (d <= 3.5f) {
            float fca = 0.5f * cospif(d / 3.5f) + 0.5f;
            int idx = atomicAdd(&ncnt, 1);
            nvx[idx] = dx; nvy[idx] = dy; nvz[idx] = dz;
            nd[idx]  = d;  nrd[idx] = 1.0f / d;
            nfc[idx] = fca; nsp[idx] = sp[tid];
        }
    }
    __syncthreads();

    // ---- angular pass: all unordered neighbor pairs ----
    const int M = ncnt;
    const int T = M * (M - 1) / 2;
    const float fm = (float)M - 0.5f;
    for (int t = tid; t < T; t += BLK) {
        // linear index -> (l1 < l2)
        int l1 = (int)(fm - sqrtf(fm * fm - 2.0f * (float)t));
        if (l1 < 0) l1 = 0;
        while (l1 * M - l1 * (l1 + 1) / 2 > t) l1--;
        while ((l1 + 1) * M - (l1 + 1) * (l1 + 2) / 2 <= t) l1++;
        int l2 = l1 + 1 + (t - (l1 * M - l1 * (l1 + 1) / 2));

        float d1 = nd[l1], d2 = nd[l2];
        float dot = nvx[l1]*nvx[l2] + nvy[l1]*nvy[l2] + nvz[l1]*nvz[l2];
        float ct = 0.95f * dot * nrd[l1] * nrd[l2];  // |ct| <= 0.95
        float st = sqrtf(fmaxf(1.0f - ct * ct, 0.0f));
        float w  = 2.0f * nfc[l1] * nfc[l2];
        float avg = 0.5f * (d1 + d2);

        float f2v[4];
        #pragma unroll
        for (int a = 0; a < 4; a++) {
            float u = avg - (0.9f + 0.65f * (float)a);
            f2v[a] = w * __expf(-8.0f * u * u);
        }

        int p = PAIRT[nsp[l1]][nsp[l2]];
        float* angp = &ang4[slice][p * 32];
        #pragma unroll
        for (int z = 0; z < 8; z++) {
            // cos(acos(ct) - shfz) = ct*cos(shfz) + st*sin(shfz)
            float c  = ct * COSZ[z] + st * SINZ[z];
            float b1 = 0.5f + 0.5f * c;
            float b2 = b1 * b1;
            float b4 = b2 * b2;
            float b8 = b4 * b4;
            float b16 = b8 * b8;
            float f1 = b16 * b16;                    // b1^32
            #pragma unroll
            for (int a = 0; a < 4; a++)
                atomicAdd(&angp[a * 8 + z], f2v[a] * f1);
        }
    }
    __syncthreads();

    // ---- reduce slices + write out ----
    float* o = aev_out + (size_t)(b * A + i) * 384;
    for (int t = tid; t < 64;  t += BLK)
        o[t] = rad4[0][t] + rad4[1][t] + rad4[2][t] + rad4[3][t];
    for (int t = tid; t < 320; t += BLK)
        o[64 + t] = ang4[0][t] + ang4[1][t] + ang4[2][t] + ang4[3][t];
    if (sp_out != nullptr && tid == 0)
        sp_out[b * A + i] = (float)sp[i];
}

extern "C" void kernel_launch(void* const* d_in, const int* in_sizes, int n_in,
                              void* d_out, int out_size)
{
    const int*   species = (const int*)d_in[0];
    const float* coords  = (const float*)d_in[1];

    const int BA = in_sizes[0];     // B*A
    const int A  = ATOMS;           // 48 per reference
    const int B  = BA / A;
    const int aev_total = BA * 384;

    float* out    = (float*)d_out;
    float* sp_out = nullptr;
    float* aev    = out;
    if (out_size >= aev_total + BA) {   // tuple output: species first, then aevs
        sp_out = out;
        aev    = out + BA;
    }

    dim3 grid(A, B);
    aev_kernel<<<grid, BLK>>>(species, coords, aev, sp_out);
}

// round 3
// speedup vs baseline: 1.9899x; 1.8048x over previous
#include <cuda_runtime.h>
#include <math.h>

#define ATOMS 48
#define CAP   48
#define BLK   128

// cos/sin of SHF_Z[z] = (2z+1)*pi/16
__device__ __constant__ float COSZ[8] = {
     0.98078528040323044913f,  0.83146961230254523708f,
     0.55557023301960222474f,  0.19509032201612826785f,
    -0.19509032201612826785f, -0.55557023301960222474f,
    -0.83146961230254523708f, -0.98078528040323044913f };
__device__ __constant__ float SINZ[8] = {
     0.19509032201612826785f,  0.55557023301960222474f,
     0.83146961230254523708f,  0.98078528040323044913f,
     0.98078528040323044913f,  0.83146961230254523708f,
     0.55557023301960222474f,  0.19509032201612826785f };

// PAIR_IDX for 4 species (upper-triangular enumeration, symmetric)
__device__ __constant__ int PAIRT[4][4] = {
    {0,1,2,3},{1,4,5,6},{2,5,7,8},{3,6,8,9} };

__global__ void __launch_bounds__(BLK)
aev_kernel(const int* __restrict__ species, const float* __restrict__ coords,
           float* __restrict__ aev_out, float* __restrict__ sp_out)
{
    const int i = blockIdx.x;          // atom within batch
    const int b = blockIdx.y;          // batch
    const int A = gridDim.x;           // 48
    const int tid = threadIdx.x;

    __shared__ float cx[ATOMS], cy[ATOMS], cz[ATOMS];
    __shared__ int   sp[ATOMS];
    __shared__ float rad8[8][64];          // 8-way sliced radial accum
    __shared__ float ang4[4][320];         // 4-way sliced angular accum
    // species-bucketed neighbor list (angular cutoff)
    __shared__ float bvx[4*CAP], bvy[4*CAP], bvz[4*CAP];
    __shared__ float bd[4*CAP], brd[4*CAP], bfc[4*CAP];
    __shared__ int   cnt[4];
    __shared__ int   jlist[CAP];           // packed: slot | (s_j << 8)
    __shared__ int   Mtot;

    const float* cb = coords + (size_t)b * A * 3;
    if (tid < A) {
        cx[tid] = cb[tid*3 + 0];
        cy[tid] = cb[tid*3 + 1];
        cz[tid] = cb[tid*3 + 2];
        sp[tid] = species[b*A + tid];
    }
    for (int t = tid; t < 8*64;  t += BLK) ((float*)rad8)[t] = 0.0f;
    for (int t = tid; t < 4*320; t += BLK) ((float*)ang4)[t] = 0.0f;
    if (tid < 4) cnt[tid] = 0;
    if (tid == 4) Mtot = 0;
    __syncthreads();

    const float xi = cx[i], yi = cy[i], zi = cz[i];

    // ---- radial pass + bucketed neighbor-list build ----
    if (tid < A && tid != i) {
        float dx = cx[tid] - xi;
        float dy = cy[tid] - yi;
        float dz = cz[tid] - zi;
        float d  = sqrtf(dx*dx + dy*dy + dz*dz);
        int   s  = sp[tid];
        if (d <= 5.2f) {
            float fcr = 0.5f * cospif(d / 5.2f) + 0.5f;
            float* radp = &rad8[tid & 7][s * 16];
            #pragma unroll
            for (int r = 0; r < 16; r++) {
                float u = d - (0.9f + 0.26875f * (float)r);
                atomicAdd(&radp[r], 0.25f * __expf(-16.0f * u * u) * fcr);
            }
        }
        if (d <= 3.5f) {
            float fca = 0.5f * cospif(d / 3.5f) + 0.5f;
            int m    = atomicAdd(&cnt[s], 1);
            int slot = s * CAP + m;
            bvx[slot] = dx; bvy[slot] = dy; bvz[slot] = dz;
            bd[slot]  = d;  brd[slot] = 1.0f / d; bfc[slot] = fca;
            int pos = atomicAdd(&Mtot, 1);
            jlist[pos] = slot | (s << 8);
        }
    }
    __syncthreads();

    // ---- angular pass: ordered pairs, grouped by (j, species_k) ----
    // Symmetric in (j,k): ordered sum with weight fc_j*fc_k == reference's
    // unordered sum with weight 2*fc_j*fc_k.
    const int M = Mtot;
    const int G = 4 * M;
    for (int g = tid; g < G; g += BLK) {
        const int jid   = jlist[g >> 2];
        const int jslot = jid & 255;
        const int sj    = jid >> 8;
        const int sk    = g & 3;

        const float jx = bvx[jslot], jy = bvy[jslot], jz = bvz[jslot];
        const float jd = bd[jslot],  jrd = brd[jslot], jfc = bfc[jslot];

        float acc[32];
        #pragma unroll
        for (int q = 0; q < 32; q++) acc[q] = 0.0f;

        const int n    = cnt[sk];
        const int base = sk * CAP;
        for (int m = 0; m < n; m++) {
            const int kslot = base + m;
            if (kslot == jslot) continue;
            float dot = jx*bvx[kslot] + jy*bvy[kslot] + jz*bvz[kslot];
            float ct  = 0.95f * dot * jrd * brd[kslot];   // |ct| <= 0.95
            float st  = sqrtf(fmaxf(1.0f - ct*ct, 0.0f));
            float avg = 0.5f * (jd + bd[kslot]);
            float w   = jfc * bfc[kslot];

            float f2v[4];
            #pragma unroll
            for (int a = 0; a < 4; a++) {
                float u = avg - (0.9f + 0.65f * (float)a);
                f2v[a] = w * __expf(-8.0f * u * u);
            }
            #pragma unroll
            for (int z = 0; z < 8; z++) {
                float c   = ct * COSZ[z] + st * SINZ[z];
                float b1  = 0.5f + 0.5f * c;
                float b2  = b1 * b1;
                float b4  = b2 * b2;
                float b8  = b4 * b4;
                float b16 = b8 * b8;
                float f1  = b16 * b16;                    // b1^32
                #pragma unroll
                for (int a = 0; a < 4; a++)
                    acc[a*8 + z] += f2v[a] * f1;
            }
        }

        const int p = PAIRT[sj][sk];
        float* angp = &ang4[tid & 3][p * 32];
        #pragma unroll
        for (int q = 0; q < 32; q++) atomicAdd(&angp[q], acc[q]);
    }
    __syncthreads();

    // ---- reduce slices + write out ----
    float* o = aev_out + (size_t)(b * A + i) * 384;
    for (int t = tid; t < 64; t += BLK) {
        float v = 0.0f;
        #pragma unroll
        for (int s8 = 0; s8 < 8; s8++) v += rad8[s8][t];
        o[t] = v;
    }
    for (int t = tid; t < 320; t += BLK)
        o[64 + t] = ang4[0][t] + ang4[1][t] + ang4[2][t] + ang4[3][t];
    if (sp_out != nullptr && tid == 0)
        sp_out[b * A + i] = (float)sp[i];
}

extern "C" void kernel_launch(void* const* d_in, const int* in_sizes, int n_in,
                              void* d_out, int out_size)
{
    const int*   species = (const int*)d_in[0];
    const float* coords  = (const float*)d_in[1];

    const int BA = in_sizes[0];     // B*A
    const int A  = ATOMS;           // 48 per reference
    const int B  = BA / A;
    const int aev_total = BA * 384;

    float* out    = (float*)d_out;
    float* sp_out = nullptr;
    float* aev    = out;
    if (out_size >= aev_total + BA) {   // tuple output: species first, then aevs
        sp_out = out;
        aev    = out + BA;
    }

    dim3 grid(A, B);
    aev_kernel<<<grid, BLK>>>(species, coords, aev, sp_out);
}

// round 4
// speedup vs baseline: 6.5293x; 3.2813x over previous
#include <cuda_runtime.h>
#include <math.h>

#define ATOMS 48
#define CAP   48          // per-species bucket capacity
#define GMAX  192         // max groups = 4 * max neighbors
#define BLK   128
#define GBS   193         // gbuf stride (conflict-free padding)

// cos/sin of SHF_Z[z] = (2z+1)*pi/16
__device__ __constant__ float COSZ[8] = {
     0.98078528040323044913f,  0.83146961230254523708f,
     0.55557023301960222474f,  0.19509032201612826785f,
    -0.19509032201612826785f, -0.55557023301960222474f,
    -0.83146961230254523708f, -0.98078528040323044913f };
__device__ __constant__ float SINZ[8] = {
     0.19509032201612826785f,  0.55557023301960222474f,
     0.83146961230254523708f,  0.98078528040323044913f,
     0.98078528040323044913f,  0.83146961230254523708f,
     0.55557023301960222474f,  0.19509032201612826785f };

// PAIR_IDX for 4 species (upper-triangular enumeration, symmetric)
__device__ __constant__ int PAIRT[4][4] = {
    {0,1,2,3},{1,4,5,6},{2,5,7,8},{3,6,8,9} };

__global__ void __launch_bounds__(BLK)
aev_kernel(const int* __restrict__ species, const float* __restrict__ coords,
           float* __restrict__ aev_out, float* __restrict__ sp_out)
{
    const int i = blockIdx.x;          // atom within batch
    const int b = blockIdx.y;          // batch
    const int A = gridDim.x;           // 48
    const int tid = threadIdx.x;

    __shared__ float cx[ATOMS], cy[ATOMS], cz[ATOMS];
    __shared__ int   sp[ATOMS];
    // angular neighbor buckets (by species): packed data
    __shared__ float4 bvec[GMAX];      // (vx, vy, vz, d)
    __shared__ float2 bsc[GMAX];       // (1/d, fc_a)
    // radial neighbor buckets (by species)
    __shared__ float2 rpak[GMAX];      // (d, 0.25*fc_r)
    __shared__ int   cnt[4], rcnt[4];
    __shared__ int   jlist[ATOMS];     // packed: slot | (s_j << 8)
    __shared__ int   Mtot;
    __shared__ int   gcnt[10];
    __shared__ int   glistP[10][CAP];  // groups per pair-class
    __shared__ float gbuf[32 * GBS];   // [feature][group] scratch

    const float* cb = coords + (size_t)b * A * 3;
    if (tid < A) {
        cx[tid] = cb[tid*3 + 0];
        cy[tid] = cb[tid*3 + 1];
        cz[tid] = cb[tid*3 + 2];
        sp[tid] = species[b*A + tid];
    }
    if (tid < 4)  { cnt[tid] = 0; rcnt[tid] = 0; }
    if (tid == 4) Mtot = 0;
    if (tid >= 8 && tid < 18) gcnt[tid - 8] = 0;
    __syncthreads();

    const float xi = cx[i], yi = cy[i], zi = cz[i];

    // ---- phase 1: distances, bucketed neighbor lists ----
    if (tid < A && tid != i) {
        float dx = cx[tid] - xi;
        float dy = cy[tid] - yi;
        float dz = cz[tid] - zi;
        float d  = sqrtf(dx*dx + dy*dy + dz*dz);
        int   s  = sp[tid];
        if (d <= 5.2f) {
            float fcr = 0.5f * cospif(d / 5.2f) + 0.5f;
            int m = atomicAdd(&rcnt[s], 1);
            rpak[s*CAP + m] = make_float2(d, 0.25f * fcr);
        }
        if (d <= 3.5f) {
            float fca = 0.5f * cospif(d / 3.5f) + 0.5f;
            int m    = atomicAdd(&cnt[s], 1);
            int slot = s*CAP + m;
            bvec[slot] = make_float4(dx, dy, dz, d);
            bsc[slot]  = make_float2(1.0f / d, fca);
            int pos = atomicAdd(&Mtot, 1);
            jlist[pos] = slot | (s << 8);
        }
    }
    __syncthreads();

    // ---- phase 2: angular groups (j, species_k), register accumulate ----
    // Ordered-pair sum with weight fc_j*fc_k == reference's unordered sum
    // with weight 2*fc_j*fc_k (integrand symmetric in j,k).
    const int M = Mtot;
    const int G = 4 * M;
    for (int g = tid; g < G; g += BLK) {
        const int jid   = jlist[g >> 2];
        const int jslot = jid & 255;
        const int sj    = jid >> 8;
        const int sk    = g & 3;

        const float4 jv = bvec[jslot];
        const float2 js = bsc[jslot];

        float acc[32];
        #pragma unroll
        for (int q = 0; q < 32; q++) acc[q] = 0.0f;

        const int n    = cnt[sk];
        const int base = sk * CAP;
        for (int m = 0; m < n; m++) {
            const int kslot = base + m;
            if (kslot == jslot) continue;
            float4 kv = bvec[kslot];
            float2 ks = bsc[kslot];
            float dot = jv.x*kv.x + jv.y*kv.y + jv.z*kv.z;
            float ct  = 0.95f * dot * js.x * ks.x;        // |ct| <= 0.95
            float st  = sqrtf(fmaxf(1.0f - ct*ct, 0.0f));
            float avg = 0.5f * (jv.w + kv.w);
            float w   = js.y * ks.y;

            float f2v[4];
            #pragma unroll
            for (int a = 0; a < 4; a++) {
                float u = avg - (0.9f + 0.65f * (float)a);
                f2v[a] = w * __expf(-8.0f * u * u);
            }
            #pragma unroll
            for (int z = 0; z < 8; z++) {
                float c   = ct * COSZ[z] + st * SINZ[z];
                float b1  = 0.5f + 0.5f * c;
                float b2  = b1 * b1;
                float b4  = b2 * b2;
                float b8  = b4 * b4;
                float b16 = b8 * b8;
                float f1  = b16 * b16;                    // b1^32
                #pragma unroll
                for (int a = 0; a < 4; a++)
                    acc[a*8 + z] += f2v[a] * f1;
            }
        }

        const int p = PAIRT[sj][sk];
        int m = atomicAdd(&gcnt[p], 1);
        glistP[p][m] = g;
        #pragma unroll
        for (int q = 0; q < 32; q++)
            gbuf[q * GBS + g] = acc[q];        // conflict-free: lanes->consec g
    }
    __syncthreads();

    // ---- phase 3: feature-per-thread reductions, direct output ----
    float* o = aev_out + (size_t)(b * A + i) * 384;

    // radial: feature (s, r); 16-lane groups share species s
    if (tid < 64) {
        const int s = tid >> 4;
        const int r = tid & 15;
        const float shf = 0.9f + 0.26875f * (float)r;
        const int n = rcnt[s];
        float acc = 0.0f;
        for (int m = 0; m < n; m++) {
            float2 v = rpak[s*CAP + m];        // broadcast within 16-lane group
            float u = v.x - shf;
            acc += v.y * __expf(-16.0f * u * u);
        }
        o[tid] = acc;
    }

    // angular: feature (p, q); each 32-lane warp-chunk = one class p
    #pragma unroll
    for (int base = 0; base < 384; base += BLK) {
        int f = base + tid;
        if (f < 320) {
            const int p = f >> 5;
            const int q = f & 31;
            const int n = gcnt[p];
            float acc = 0.0f;
            for (int m = 0; m < n; m++) {
                int g = glistP[p][m];          // broadcast
                acc += gbuf[q * GBS + g];      // conflict-free: lanes->consec q
            }
            o[64 + f] = acc;
        }
    }

    if (sp_out != nullptr && tid == 0)
        sp_out[b * A + i] = (float)sp[i];
}

extern "C" void kernel_launch(void* const* d_in, const int* in_sizes, int n_in,
                              void* d_out, int out_size)
{
    const int*   species = (const int*)d_in[0];
    const float* coords  = (const float*)d_in[1];

    const int BA = in_sizes[0];     // B*A
    const int A  = ATOMS;           // 48 per reference
    const int B  = BA / A;
    const int aev_total = BA * 384;

    float* out    = (float*)d_out;
    float* sp_out = nullptr;
    float* aev    = out;
    if (out_size >= aev_total + BA) {   // tuple output: species first, then aevs
        sp_out = out;
        aev    = out + BA;
    }

    dim3 grid(A, B);
    aev_kernel<<<grid, BLK>>>(species, coords, aev, sp_out);
}